// round 2
// baseline (speedup 1.0000x reference)
#include <cuda_runtime.h>

// ============================================================================
// SpectralMoEHeads: out[bt, h*64+o] = sum_k S[bt,k] * sum_i x[bt,h*64+i]*W[h,k,i,o]
//   S[bt,k] = phi[bt%2048, k] + sum_i x[bt,i]*diag[k,i]
// B*T = 8192 tokens, H=16, K=8, d_h=d_o=64, D=1024.
//
// Kernel 1: scores  -> g_scores[8192][8]
// Kernel 2: per (token-tile 128, head) GEMM [128x512]x[512x64] via
//           mma.sync.m16n8k8 tf32, with A = S[t,k]*x[t,i] built in registers.
// ============================================================================

__device__ float g_scores[8192 * 8];

__device__ __forceinline__ unsigned f2tf32(float f) {
    unsigned u;
    asm("cvt.rna.tf32.f32 %0, %1;" : "=r"(u) : "f"(f));
    return u;
}

__device__ __forceinline__ void mma_tf32(float& c0, float& c1, float& c2, float& c3,
                                         unsigned a0, unsigned a1, unsigned a2, unsigned a3,
                                         unsigned b0, unsigned b1) {
    asm volatile(
        "mma.sync.aligned.m16n8k8.row.col.f32.tf32.tf32.f32 "
        "{%0,%1,%2,%3}, {%4,%5,%6,%7}, {%8,%9}, {%0,%1,%2,%3};\n"
        : "+f"(c0), "+f"(c1), "+f"(c2), "+f"(c3)
        : "r"(a0), "r"(a1), "r"(a2), "r"(a3), "r"(b0), "r"(b1));
}

// ---------------------------------------------------------------------------
// Scores kernel: 32 tokens per CTA, 256 threads, thread = (token, k).
// smem: diag [8][1028] (pad => conflict-free), x tile [32][1024].
// ---------------------------------------------------------------------------
#define SC_SMEM_FLOATS (8 * 1028 + 32 * 1024)

__global__ __launch_bounds__(256) void scores_kernel(
    const float* __restrict__ x, const float* __restrict__ diag,
    const float* __restrict__ phi)
{
    extern __shared__ float sm[];
    float* diag_s = sm;              // 8 * 1028
    float* x_s    = sm + 8 * 1028;   // 32 * 1024

    const int tid = threadIdx.x;
    const int bt0 = blockIdx.x * 32;

    // load diag: 8192 floats = 2048 float4
    for (int idx = tid; idx < 2048; idx += 256) {
        int r = idx >> 8, c4 = idx & 255;
        float4 v = ((const float4*)diag)[r * 256 + c4];
        float* d = diag_s + r * 1028 + c4 * 4;
        d[0] = v.x; d[1] = v.y; d[2] = v.z; d[3] = v.w;
    }
    // load x tile: 32*1024 floats = 8192 float4
    for (int idx = tid; idx < 8192; idx += 256) {
        int r = idx >> 8, c4 = idx & 255;
        ((float4*)(x_s + r * 1024))[c4] =
            ((const float4*)x)[(size_t)(bt0 + r) * 256 + c4];
    }
    __syncthreads();

    const int t = tid >> 3, k = tid & 7;
    const float4* xr4 = (const float4*)(x_s + t * 1024);
    const float4* dr4 = (const float4*)(diag_s + k * 1028);
    float a0 = 0.f, a1 = 0.f, a2 = 0.f, a3 = 0.f;
#pragma unroll 8
    for (int c = 0; c < 256; ++c) {
        float4 xv = xr4[c];
        float4 dv = dr4[c];
        a0 = fmaf(xv.x, dv.x, a0);
        a1 = fmaf(xv.y, dv.y, a1);
        a2 = fmaf(xv.z, dv.z, a2);
        a3 = fmaf(xv.w, dv.w, a3);
    }
    const int bt = bt0 + t;
    g_scores[bt * 8 + k] = phi[(bt & 2047) * 8 + k] + ((a0 + a1) + (a2 + a3));
}

// ---------------------------------------------------------------------------
// Main kernel: CTA = (token tile of 128, head). 256 threads = 8 warps,
// warp grid 4(m) x 2(n), warp tile 32x32, mma m16n8k8 tf32.
// smem: x_s [128][68] f32, W_s [2][64][72] tf32(u32), S_s [128][9] f32.
// ---------------------------------------------------------------------------
#define XS_STRIDE 68
#define WS_STRIDE 72
#define WS_BUF    (64 * WS_STRIDE)          // 4608 u32 per buffer
#define SS_STRIDE 9
#define MAIN_SMEM_FLOATS (128 * XS_STRIDE + 2 * WS_BUF + 128 * SS_STRIDE)

__global__ __launch_bounds__(256) void spectral_main_kernel(
    const float* __restrict__ x, const float* __restrict__ w,
    float* __restrict__ out)
{
    extern __shared__ float sm[];
    float*    x_s = sm;                                   // 128 * 68
    unsigned* W_s = (unsigned*)(sm + 128 * XS_STRIDE);    // 2 * 64 * 72
    float*    S_s = sm + 128 * XS_STRIDE + 2 * WS_BUF;    // 128 * 9

    const int tid  = threadIdx.x;
    const int h    = blockIdx.y;
    const int bt0  = blockIdx.x * 128;

    const int lane = tid & 31;
    const int wid  = tid >> 5;
    const int gid  = lane >> 2;   // 0..7
    const int tig  = lane & 3;    // 0..3
    const int wm   = wid & 3;     // m warp coord (x32)
    const int wn   = wid >> 2;    // n warp coord (x32)

    const float* Wh = w + (size_t)h * 8 * 64 * 64;   // W[h] : [512][64]

    // ---- stage x tile (128 rows x 64 cols = 2048 float4) ----
    for (int j = 0; j < 8; ++j) {
        int idx = tid + j * 256;            // 0..2047
        int r = idx >> 4, c4 = idx & 15;
        float4 v = ((const float4*)x)[(size_t)(bt0 + r) * 256 + h * 16 + c4];
        float* d = x_s + r * XS_STRIDE + c4 * 4;
        d[0] = v.x; d[1] = v.y; d[2] = v.z; d[3] = v.w;
    }
    // ---- stage scores (128 x 8 = 1024 floats) ----
    for (int j = 0; j < 4; ++j) {
        int idx = tid + j * 256;
        int r = idx >> 3, k = idx & 7;
        S_s[r * SS_STRIDE + k] = g_scores[(bt0 + r) * 8 + k];
    }
    // ---- stage W chunk k=0 into buffer 0 (64x64 f32 -> tf32) ----
    {
        const float4* src = (const float4*)Wh;
        for (int j = 0; j < 4; ++j) {
            int idx = tid + j * 256;        // 0..1023
            int r = idx >> 4, c4 = idx & 15;
            float4 v = src[idx];
            unsigned* d = W_s + r * WS_STRIDE + c4 * 4;
            ((uint4*)d)[0] = make_uint4(f2tf32(v.x), f2tf32(v.y), f2tf32(v.z), f2tf32(v.w));
        }
    }
    __syncthreads();

    // ---- load x fragments into registers (reused across all 8 k-chunks) ----
    float xf[2][8][4];
#pragma unroll
    for (int mt = 0; mt < 2; ++mt) {
        const int t0 = wm * 32 + mt * 16 + gid;
        const int t1 = t0 + 8;
#pragma unroll
        for (int it = 0; it < 8; ++it) {
            const int i0 = it * 8 + tig;
            xf[mt][it][0] = x_s[t0 * XS_STRIDE + i0];
            xf[mt][it][1] = x_s[t1 * XS_STRIDE + i0];
            xf[mt][it][2] = x_s[t0 * XS_STRIDE + i0 + 4];
            xf[mt][it][3] = x_s[t1 * XS_STRIDE + i0 + 4];
        }
    }

    float acc[2][4][4];
#pragma unroll
    for (int mt = 0; mt < 2; ++mt)
#pragma unroll
        for (int nt = 0; nt < 4; ++nt)
#pragma unroll
            for (int r = 0; r < 4; ++r) acc[mt][nt][r] = 0.f;

    int buf = 0;
#pragma unroll 1
    for (int k = 0; k < 8; ++k) {
        // prefetch next W chunk into registers (overlaps with MMA below)
        float4 wr0, wr1, wr2, wr3;
        if (k < 7) {
            const float4* src = (const float4*)(Wh + (size_t)(k + 1) * 4096);
            wr0 = src[tid];
            wr1 = src[tid + 256];
            wr2 = src[tid + 512];
            wr3 = src[tid + 768];
        }

        // per-k score scalars for this warp's 4 token rows
        const int tb = wm * 32 + gid;
        const float s00 = S_s[(tb)      * SS_STRIDE + k];   // mt0, rows gid
        const float s01 = S_s[(tb + 8)  * SS_STRIDE + k];   // mt0, rows gid+8
        const float s10 = S_s[(tb + 16) * SS_STRIDE + k];   // mt1, rows gid
        const float s11 = S_s[(tb + 24) * SS_STRIDE + k];   // mt1, rows gid+8

        const unsigned* Wb = W_s + buf * WS_BUF;

#pragma unroll
        for (int it = 0; it < 8; ++it) {
            unsigned a0[4], a1[4];
            a0[0] = f2tf32(s00 * xf[0][it][0]);
            a0[1] = f2tf32(s01 * xf[0][it][1]);
            a0[2] = f2tf32(s00 * xf[0][it][2]);
            a0[3] = f2tf32(s01 * xf[0][it][3]);
            a1[0] = f2tf32(s10 * xf[1][it][0]);
            a1[1] = f2tf32(s11 * xf[1][it][1]);
            a1[2] = f2tf32(s10 * xf[1][it][2]);
            a1[3] = f2tf32(s11 * xf[1][it][3]);

            const int row0 = (it * 8 + tig) * WS_STRIDE + wn * 32 + gid;
            const int row1 = row0 + 4 * WS_STRIDE;
#pragma unroll
            for (int nt = 0; nt < 4; ++nt) {
                unsigned b0 = Wb[row0 + nt * 8];
                unsigned b1 = Wb[row1 + nt * 8];
                mma_tf32(acc[0][nt][0], acc[0][nt][1], acc[0][nt][2], acc[0][nt][3],
                         a0[0], a0[1], a0[2], a0[3], b0, b1);
                mma_tf32(acc[1][nt][0], acc[1][nt][1], acc[1][nt][2], acc[1][nt][3],
                         a1[0], a1[1], a1[2], a1[3], b0, b1);
            }
        }

        if (k < 7) {
            // write prefetched chunk into the other buffer; all warps are past
            // the previous barrier, so no one still reads buf^1.
            unsigned* dbuf = W_s + (buf ^ 1) * WS_BUF;
            {
                int idx = tid;           int r = idx >> 4, c4 = idx & 15;
                ((uint4*)(dbuf + r * WS_STRIDE + c4 * 4))[0] =
                    make_uint4(f2tf32(wr0.x), f2tf32(wr0.y), f2tf32(wr0.z), f2tf32(wr0.w));
            }
            {
                int idx = tid + 256;     int r = idx >> 4, c4 = idx & 15;
                ((uint4*)(dbuf + r * WS_STRIDE + c4 * 4))[0] =
                    make_uint4(f2tf32(wr1.x), f2tf32(wr1.y), f2tf32(wr1.z), f2tf32(wr1.w));
            }
            {
                int idx = tid + 512;     int r = idx >> 4, c4 = idx & 15;
                ((uint4*)(dbuf + r * WS_STRIDE + c4 * 4))[0] =
                    make_uint4(f2tf32(wr2.x), f2tf32(wr2.y), f2tf32(wr2.z), f2tf32(wr2.w));
            }
            {
                int idx = tid + 768;     int r = idx >> 4, c4 = idx & 15;
                ((uint4*)(dbuf + r * WS_STRIDE + c4 * 4))[0] =
                    make_uint4(f2tf32(wr3.x), f2tf32(wr3.y), f2tf32(wr3.z), f2tf32(wr3.w));
            }
            __syncthreads();
            buf ^= 1;
        }
    }

    // ---- epilogue: fp32 store ----
#pragma unroll
    for (int mt = 0; mt < 2; ++mt) {
        const int t0 = bt0 + wm * 32 + mt * 16 + gid;
#pragma unroll
        for (int nt = 0; nt < 4; ++nt) {
            const int o = h * 64 + wn * 32 + nt * 8 + tig * 2;
            *(float2*)(out + (size_t)t0 * 1024 + o) =
                make_float2(acc[mt][nt][0], acc[mt][nt][1]);
            *(float2*)(out + (size_t)(t0 + 8) * 1024 + o) =
                make_float2(acc[mt][nt][2], acc[mt][nt][3]);
        }
    }
}

// ---------------------------------------------------------------------------
extern "C" void kernel_launch(void* const* d_in, const int* in_sizes, int n_in,
                              void* d_out, int out_size) {
    const float* x    = (const float*)d_in[0];   // [4,2048,1024]
    const float* wgt  = (const float*)d_in[1];   // [16,8,64,64]
    const float* diag = (const float*)d_in[2];   // [8,1024]
    const float* phi  = (const float*)d_in[3];   // [2048,8]
    float* out = (float*)d_out;                  // [4,2048,1024]

    const int sc_smem   = SC_SMEM_FLOATS * 4;
    const int main_smem = MAIN_SMEM_FLOATS * 4;
    cudaFuncSetAttribute(scores_kernel,
                         cudaFuncAttributeMaxDynamicSharedMemorySize, sc_smem);
    cudaFuncSetAttribute(spectral_main_kernel,
                         cudaFuncAttributeMaxDynamicSharedMemorySize, main_smem);

    scores_kernel<<<256, 256, sc_smem>>>(x, diag, phi);
    spectral_main_kernel<<<dim3(64, 16), 256, main_smem>>>(x, wgt, out);
}

// round 4
// speedup vs baseline: 1.2783x; 1.2783x over previous
#include <cuda_runtime.h>

// ============================================================================
// SpectralMoEHeads: out[bt, h*64+o] = sum_k S[bt,k] * sum_i x[bt,h*64+i]*W[h,k,i,o]
//   S[bt,k] = phi[bt%2048, k] + sum_i x[bt,i]*diag[k,i]
//
// Kernel 1: scores  -> g_scores[8192][8]   (warp = 4 tokens, diag in regs)
// Kernel 2: per (token-tile 128, head) GEMM via mma.sync.m16n8k8 tf32.
//   Restructure vs R0: A = tf32(x) converted ONCE; per k-chunk compute
//   Y_k = x*W_k fresh (zero-C MMA on first it), then acc += S[t,k]*Y_k.
//   Removes 1024 cvt/mul per thread from the mainloop.
// ============================================================================

__device__ float g_scores[8192 * 8];

__device__ __forceinline__ unsigned f2tf32(float f) {
    unsigned u;
    asm("cvt.rna.tf32.f32 %0, %1;" : "=r"(u) : "f"(f));
    return u;
}

// acc += A*B
__device__ __forceinline__ void mma_tf32_acc(float& c0, float& c1, float& c2, float& c3,
                                             unsigned a0, unsigned a1, unsigned a2, unsigned a3,
                                             unsigned b0, unsigned b1) {
    asm volatile(
        "mma.sync.aligned.m16n8k8.row.col.f32.tf32.tf32.f32 "
        "{%0,%1,%2,%3}, {%4,%5,%6,%7}, {%8,%9}, {%0,%1,%2,%3};\n"
        : "+f"(c0), "+f"(c1), "+f"(c2), "+f"(c3)
        : "r"(a0), "r"(a1), "r"(a2), "r"(a3), "r"(b0), "r"(b1));
}

// d = A*B (fresh accumulator, C = 0)
__device__ __forceinline__ void mma_tf32_set(float& d0, float& d1, float& d2, float& d3,
                                             unsigned a0, unsigned a1, unsigned a2, unsigned a3,
                                             unsigned b0, unsigned b1) {
    asm volatile(
        "mma.sync.aligned.m16n8k8.row.col.f32.tf32.tf32.f32 "
        "{%0,%1,%2,%3}, {%4,%5,%6,%7}, {%8,%9}, {%10,%11,%12,%13};\n"
        : "=f"(d0), "=f"(d1), "=f"(d2), "=f"(d3)
        : "r"(a0), "r"(a1), "r"(a2), "r"(a3), "r"(b0), "r"(b1),
          "f"(0.f), "f"(0.f), "f"(0.f), "f"(0.f));
}

// ---------------------------------------------------------------------------
// Scores kernel: 256 threads = 8 warps, warp handles 4 tokens.
// diag (32KB) in smem, fragments hoisted to registers per column chunk and
// reused across the warp's 4 tokens (LDS traffic /4 vs thread-per-token).
// ---------------------------------------------------------------------------
__global__ __launch_bounds__(256) void scores_kernel(
    const float* __restrict__ x, const float* __restrict__ diag,
    const float* __restrict__ phi)
{
    __shared__ float4 diag_s[8 * 256];   // 32 KB

    const int tid = threadIdx.x;
    for (int i = tid; i < 2048; i += 256) diag_s[i] = ((const float4*)diag)[i];
    __syncthreads();

    const int lane = tid & 31;
    const int w    = tid >> 5;
    const int t0   = (blockIdx.x * 8 + w) * 4;

    float acc[4][8];
#pragma unroll
    for (int t = 0; t < 4; ++t)
#pragma unroll
        for (int k = 0; k < 8; ++k) acc[t][k] = 0.f;

#pragma unroll
    for (int c = 0; c < 8; ++c) {
        float4 dv[8];
#pragma unroll
        for (int k = 0; k < 8; ++k) dv[k] = diag_s[k * 256 + c * 32 + lane];
#pragma unroll
        for (int t = 0; t < 4; ++t) {
            float4 xv = ((const float4*)x)[(size_t)(t0 + t) * 256 + c * 32 + lane];
#pragma unroll
            for (int k = 0; k < 8; ++k) {
                acc[t][k] = fmaf(xv.x, dv[k].x, acc[t][k]);
                acc[t][k] = fmaf(xv.y, dv[k].y, acc[t][k]);
                acc[t][k] = fmaf(xv.z, dv[k].z, acc[t][k]);
                acc[t][k] = fmaf(xv.w, dv[k].w, acc[t][k]);
            }
        }
    }

    // butterfly reduce across the warp
#pragma unroll
    for (int t = 0; t < 4; ++t)
#pragma unroll
        for (int k = 0; k < 8; ++k) {
            float v = acc[t][k];
            v += __shfl_xor_sync(0xffffffffu, v, 16);
            v += __shfl_xor_sync(0xffffffffu, v, 8);
            v += __shfl_xor_sync(0xffffffffu, v, 4);
            v += __shfl_xor_sync(0xffffffffu, v, 2);
            v += __shfl_xor_sync(0xffffffffu, v, 1);
            acc[t][k] = v;
        }

    if (lane == 0) {
#pragma unroll
        for (int t = 0; t < 4; ++t) {
            const int bt = t0 + t;
            float4 p0 = ((const float4*)phi)[(bt & 2047) * 2];
            float4 p1 = ((const float4*)phi)[(bt & 2047) * 2 + 1];
            float4 r0 = make_float4(acc[t][0] + p0.x, acc[t][1] + p0.y,
                                    acc[t][2] + p0.z, acc[t][3] + p0.w);
            float4 r1 = make_float4(acc[t][4] + p1.x, acc[t][5] + p1.y,
                                    acc[t][6] + p1.z, acc[t][7] + p1.w);
            ((float4*)g_scores)[bt * 2]     = r0;
            ((float4*)g_scores)[bt * 2 + 1] = r1;
        }
    }
}

// ---------------------------------------------------------------------------
// Main kernel: CTA = (token tile of 128, head). 256 threads = 8 warps,
// warp grid 4(m) x 2(n), warp tile 32x32, mma m16n8k8 tf32.
// smem: x_s [128][68] f32, W_s [2][64][72] tf32(u32), S_s [128][9] f32.
// ---------------------------------------------------------------------------
#define XS_STRIDE 68
#define WS_STRIDE 72
#define WS_BUF    (64 * WS_STRIDE)
#define SS_STRIDE 9
#define MAIN_SMEM_FLOATS (128 * XS_STRIDE + 2 * WS_BUF + 128 * SS_STRIDE)

__global__ __launch_bounds__(256) void spectral_main_kernel(
    const float* __restrict__ x, const float* __restrict__ w,
    float* __restrict__ out)
{
    extern __shared__ float sm[];
    float*    x_s = sm;                                   // 128 * 68
    unsigned* W_s = (unsigned*)(sm + 128 * XS_STRIDE);    // 2 * 64 * 72
    float*    S_s = sm + 128 * XS_STRIDE + 2 * WS_BUF;    // 128 * 9

    const int tid  = threadIdx.x;
    const int h    = blockIdx.y;
    const int bt0  = blockIdx.x * 128;

    const int lane = tid & 31;
    const int wid  = tid >> 5;
    const int gid  = lane >> 2;   // 0..7
    const int tig  = lane & 3;    // 0..3
    const int wm   = wid & 3;     // m warp coord (x32)
    const int wn   = wid >> 2;    // n warp coord (x32)

    const float* Wh = w + (size_t)h * 8 * 64 * 64;   // W[h] : [512][64]

    // ---- stage x tile (128 rows x 64 cols) ----
    for (int j = 0; j < 8; ++j) {
        int idx = tid + j * 256;
        int r = idx >> 4, c4 = idx & 15;
        float4 v = ((const float4*)x)[(size_t)(bt0 + r) * 256 + h * 16 + c4];
        float* d = x_s + r * XS_STRIDE + c4 * 4;
        d[0] = v.x; d[1] = v.y; d[2] = v.z; d[3] = v.w;
    }
    // ---- stage scores ----
    for (int j = 0; j < 4; ++j) {
        int idx = tid + j * 256;
        int r = idx >> 3, k = idx & 7;
        S_s[r * SS_STRIDE + k] = g_scores[(bt0 + r) * 8 + k];
    }
    // ---- stage W chunk k=0 into buffer 0 (f32 -> tf32) ----
    {
        const float4* src = (const float4*)Wh;
        for (int j = 0; j < 4; ++j) {
            int idx = tid + j * 256;
            int r = idx >> 4, c4 = idx & 15;
            float4 v = src[idx];
            unsigned* d = W_s + r * WS_STRIDE + c4 * 4;
            ((uint4*)d)[0] = make_uint4(f2tf32(v.x), f2tf32(v.y), f2tf32(v.z), f2tf32(v.w));
        }
    }
    __syncthreads();

    // ---- x fragments, converted to tf32 ONCE (reused for all 8 k-chunks) ----
    unsigned xf[2][8][4];
#pragma unroll
    for (int mt = 0; mt < 2; ++mt) {
        const int t0 = wm * 32 + mt * 16 + gid;
        const int t1 = t0 + 8;
#pragma unroll
        for (int it = 0; it < 8; ++it) {
            const int i0 = it * 8 + tig;
            xf[mt][it][0] = f2tf32(x_s[t0 * XS_STRIDE + i0]);
            xf[mt][it][1] = f2tf32(x_s[t1 * XS_STRIDE + i0]);
            xf[mt][it][2] = f2tf32(x_s[t0 * XS_STRIDE + i0 + 4]);
            xf[mt][it][3] = f2tf32(x_s[t1 * XS_STRIDE + i0 + 4]);
        }
    }

    float acc[2][4][4];
#pragma unroll
    for (int mt = 0; mt < 2; ++mt)
#pragma unroll
        for (int nt = 0; nt < 4; ++nt)
#pragma unroll
            for (int r = 0; r < 4; ++r) acc[mt][nt][r] = 0.f;

    int buf = 0;
#pragma unroll 1
    for (int k = 0; k < 8; ++k) {
        // prefetch next W chunk into registers (overlaps with MMA below)
        float4 wr0, wr1, wr2, wr3;
        if (k < 7) {
            const float4* src = (const float4*)(Wh + (size_t)(k + 1) * 4096);
            wr0 = src[tid];
            wr1 = src[tid + 256];
            wr2 = src[tid + 512];
            wr3 = src[tid + 768];
        }

        // per-k score scalars for this warp's 4 token rows
        const int tb = wm * 32 + gid;
        const float s00 = S_s[(tb)      * SS_STRIDE + k];
        const float s01 = S_s[(tb + 8)  * SS_STRIDE + k];
        const float s10 = S_s[(tb + 16) * SS_STRIDE + k];
        const float s11 = S_s[(tb + 24) * SS_STRIDE + k];

        const unsigned* Wb = W_s + buf * WS_BUF;

        // Y_k = x * W_k  (unscaled, fresh accumulators via zero-C MMA)
        float acck[2][4][4];
#pragma unroll
        for (int it = 0; it < 8; ++it) {
            const int row0 = (it * 8 + tig) * WS_STRIDE + wn * 32 + gid;
            const int row1 = row0 + 4 * WS_STRIDE;
#pragma unroll
            for (int nt = 0; nt < 4; ++nt) {
                unsigned b0 = Wb[row0 + nt * 8];
                unsigned b1 = Wb[row1 + nt * 8];
                if (it == 0) {
                    mma_tf32_set(acck[0][nt][0], acck[0][nt][1], acck[0][nt][2], acck[0][nt][3],
                                 xf[0][it][0], xf[0][it][1], xf[0][it][2], xf[0][it][3], b0, b1);
                    mma_tf32_set(acck[1][nt][0], acck[1][nt][1], acck[1][nt][2], acck[1][nt][3],
                                 xf[1][it][0], xf[1][it][1], xf[1][it][2], xf[1][it][3], b0, b1);
                } else {
                    mma_tf32_acc(acck[0][nt][0], acck[0][nt][1], acck[0][nt][2], acck[0][nt][3],
                                 xf[0][it][0], xf[0][it][1], xf[0][it][2], xf[0][it][3], b0, b1);
                    mma_tf32_acc(acck[1][nt][0], acck[1][nt][1], acck[1][nt][2], acck[1][nt][3],
                                 xf[1][it][0], xf[1][it][1], xf[1][it][2], xf[1][it][3], b0, b1);
                }
            }
        }

        // acc += S[t,k] * Y_k   (c0,c1 -> row gid : s*0 ; c2,c3 -> row gid+8 : s*1)
#pragma unroll
        for (int nt = 0; nt < 4; ++nt) {
            acc[0][nt][0] = fmaf(s00, acck[0][nt][0], acc[0][nt][0]);
            acc[0][nt][1] = fmaf(s00, acck[0][nt][1], acc[0][nt][1]);
            acc[0][nt][2] = fmaf(s01, acck[0][nt][2], acc[0][nt][2]);
            acc[0][nt][3] = fmaf(s01, acck[0][nt][3], acc[0][nt][3]);
            acc[1][nt][0] = fmaf(s10, acck[1][nt][0], acc[1][nt][0]);
            acc[1][nt][1] = fmaf(s10, acck[1][nt][1], acc[1][nt][1]);
            acc[1][nt][2] = fmaf(s11, acck[1][nt][2], acc[1][nt][2]);
            acc[1][nt][3] = fmaf(s11, acck[1][nt][3], acc[1][nt][3]);
        }

        if (k < 7) {
            unsigned* dbuf = W_s + (buf ^ 1) * WS_BUF;
            {
                int idx = tid;           int r = idx >> 4, c4 = idx & 15;
                ((uint4*)(dbuf + r * WS_STRIDE + c4 * 4))[0] =
                    make_uint4(f2tf32(wr0.x), f2tf32(wr0.y), f2tf32(wr0.z), f2tf32(wr0.w));
            }
            {
                int idx = tid + 256;     int r = idx >> 4, c4 = idx & 15;
                ((uint4*)(dbuf + r * WS_STRIDE + c4 * 4))[0] =
                    make_uint4(f2tf32(wr1.x), f2tf32(wr1.y), f2tf32(wr1.z), f2tf32(wr1.w));
            }
            {
                int idx = tid + 512;     int r = idx >> 4, c4 = idx & 15;
                ((uint4*)(dbuf + r * WS_STRIDE + c4 * 4))[0] =
                    make_uint4(f2tf32(wr2.x), f2tf32(wr2.y), f2tf32(wr2.z), f2tf32(wr2.w));
            }
            {
                int idx = tid + 768;     int r = idx >> 4, c4 = idx & 15;
                ((uint4*)(dbuf + r * WS_STRIDE + c4 * 4))[0] =
                    make_uint4(f2tf32(wr3.x), f2tf32(wr3.y), f2tf32(wr3.z), f2tf32(wr3.w));
            }
            __syncthreads();
            buf ^= 1;
        }
    }

    // ---- epilogue: fp32 store ----
#pragma unroll
    for (int mt = 0; mt < 2; ++mt) {
        const int t0 = bt0 + wm * 32 + mt * 16 + gid;
#pragma unroll
        for (int nt = 0; nt < 4; ++nt) {
            const int o = h * 64 + wn * 32 + nt * 8 + tig * 2;
            *(float2*)(out + (size_t)t0 * 1024 + o) =
                make_float2(acc[mt][nt][0], acc[mt][nt][1]);
            *(float2*)(out + (size_t)(t0 + 8) * 1024 + o) =
                make_float2(acc[mt][nt][2], acc[mt][nt][3]);
        }
    }
}

// ---------------------------------------------------------------------------
extern "C" void kernel_launch(void* const* d_in, const int* in_sizes, int n_in,
                              void* d_out, int out_size) {
    const float* x    = (const float*)d_in[0];   // [4,2048,1024]
    const float* wgt  = (const float*)d_in[1];   // [16,8,64,64]
    const float* diag = (const float*)d_in[2];   // [8,1024]
    const float* phi  = (const float*)d_in[3];   // [2048,8]
    float* out = (float*)d_out;                  // [4,2048,1024]

    const int main_smem = MAIN_SMEM_FLOATS * 4;
    cudaFuncSetAttribute(spectral_main_kernel,
                         cudaFuncAttributeMaxDynamicSharedMemorySize, main_smem);

    scores_kernel<<<256, 256>>>(x, diag, phi);
    spectral_main_kernel<<<dim3(64, 16), 256, main_smem>>>(x, wgt, out);
}

// round 7
// speedup vs baseline: 1.5325x; 1.1989x over previous
#include <cuda_runtime.h>

// ============================================================================
// SpectralMoEHeads: out[bt, h*64+o] = sum_k S[bt,k] * sum_i x[bt,h*64+i]*W[h,k,i,o]
//   S[bt,k] = phi[bt%2048, k] + sum_i x[bt,i]*diag[k,i]
//
// R4 changes vs R2:
//  - W staged via cp.async (raw f32 -> smem, fed to mma.tf32 as truncated tf32):
//    removes prefetch registers, LDG/cvt/STS from mainloop.
//  - nt-outer MMA loop: acck shrinks 32 -> 8 regs.
//  - __launch_bounds__(256, 2): <=128 regs -> 2 CTAs/SM (occ 12.5% -> 25%).
// ============================================================================

__device__ float g_scores[8192 * 8];

__device__ __forceinline__ unsigned f2tf32(float f) {
    unsigned u;
    asm("cvt.rna.tf32.f32 %0, %1;" : "=r"(u) : "f"(f));
    return u;
}

__device__ __forceinline__ void mma_tf32_acc(float& c0, float& c1, float& c2, float& c3,
                                             unsigned a0, unsigned a1, unsigned a2, unsigned a3,
                                             unsigned b0, unsigned b1) {
    asm volatile(
        "mma.sync.aligned.m16n8k8.row.col.f32.tf32.tf32.f32 "
        "{%0,%1,%2,%3}, {%4,%5,%6,%7}, {%8,%9}, {%0,%1,%2,%3};\n"
        : "+f"(c0), "+f"(c1), "+f"(c2), "+f"(c3)
        : "r"(a0), "r"(a1), "r"(a2), "r"(a3), "r"(b0), "r"(b1));
}

__device__ __forceinline__ void mma_tf32_set(float& d0, float& d1, float& d2, float& d3,
                                             unsigned a0, unsigned a1, unsigned a2, unsigned a3,
                                             unsigned b0, unsigned b1) {
    asm volatile(
        "mma.sync.aligned.m16n8k8.row.col.f32.tf32.tf32.f32 "
        "{%0,%1,%2,%3}, {%4,%5,%6,%7}, {%8,%9}, {%10,%11,%12,%13};\n"
        : "=f"(d0), "=f"(d1), "=f"(d2), "=f"(d3)
        : "r"(a0), "r"(a1), "r"(a2), "r"(a3), "r"(b0), "r"(b1),
          "f"(0.f), "f"(0.f), "f"(0.f), "f"(0.f));
}

__device__ __forceinline__ void cp_async16(unsigned dst_smem, const void* src) {
    asm volatile("cp.async.cg.shared.global [%0], [%1], 16;\n"
                 :: "r"(dst_smem), "l"(src) : "memory");
}
__device__ __forceinline__ void cp_commit() {
    asm volatile("cp.async.commit_group;\n" ::: "memory");
}
template <int N>
__device__ __forceinline__ void cp_wait() {
    asm volatile("cp.async.wait_group %0;\n" :: "n"(N) : "memory");
}

// ---------------------------------------------------------------------------
// Scores kernel (unchanged; ~6.5us, near its DRAM floor)
// ---------------------------------------------------------------------------
__global__ __launch_bounds__(256) void scores_kernel(
    const float* __restrict__ x, const float* __restrict__ diag,
    const float* __restrict__ phi)
{
    __shared__ float4 diag_s[8 * 256];

    const int tid = threadIdx.x;
    for (int i = tid; i < 2048; i += 256) diag_s[i] = ((const float4*)diag)[i];
    __syncthreads();

    const int lane = tid & 31;
    const int w    = tid >> 5;
    const int t0   = (blockIdx.x * 8 + w) * 4;

    float acc[4][8];
#pragma unroll
    for (int t = 0; t < 4; ++t)
#pragma unroll
        for (int k = 0; k < 8; ++k) acc[t][k] = 0.f;

#pragma unroll
    for (int c = 0; c < 8; ++c) {
        float4 dv[8];
#pragma unroll
        for (int k = 0; k < 8; ++k) dv[k] = diag_s[k * 256 + c * 32 + lane];
#pragma unroll
        for (int t = 0; t < 4; ++t) {
            float4 xv = ((const float4*)x)[(size_t)(t0 + t) * 256 + c * 32 + lane];
#pragma unroll
            for (int k = 0; k < 8; ++k) {
                acc[t][k] = fmaf(xv.x, dv[k].x, acc[t][k]);
                acc[t][k] = fmaf(xv.y, dv[k].y, acc[t][k]);
                acc[t][k] = fmaf(xv.z, dv[k].z, acc[t][k]);
                acc[t][k] = fmaf(xv.w, dv[k].w, acc[t][k]);
            }
        }
    }

#pragma unroll
    for (int t = 0; t < 4; ++t)
#pragma unroll
        for (int k = 0; k < 8; ++k) {
            float v = acc[t][k];
            v += __shfl_xor_sync(0xffffffffu, v, 16);
            v += __shfl_xor_sync(0xffffffffu, v, 8);
            v += __shfl_xor_sync(0xffffffffu, v, 4);
            v += __shfl_xor_sync(0xffffffffu, v, 2);
            v += __shfl_xor_sync(0xffffffffu, v, 1);
            acc[t][k] = v;
        }

    if (lane == 0) {
#pragma unroll
        for (int t = 0; t < 4; ++t) {
            const int bt = t0 + t;
            float4 p0 = ((const float4*)phi)[(bt & 2047) * 2];
            float4 p1 = ((const float4*)phi)[(bt & 2047) * 2 + 1];
            float4 r0 = make_float4(acc[t][0] + p0.x, acc[t][1] + p0.y,
                                    acc[t][2] + p0.z, acc[t][3] + p0.w);
            float4 r1 = make_float4(acc[t][4] + p1.x, acc[t][5] + p1.y,
                                    acc[t][6] + p1.z, acc[t][7] + p1.w);
            ((float4*)g_scores)[bt * 2]     = r0;
            ((float4*)g_scores)[bt * 2 + 1] = r1;
        }
    }
}

// ---------------------------------------------------------------------------
// Main kernel: CTA = (token tile 128, head). 256 threads = 8 warps,
// warp grid 4(m) x 2(n), warp tile 32x32, mma m16n8k8 tf32.
// smem: x_s [128][68] f32, Wraw [2][64][72] raw f32 (cp.async), S_s [128][9].
// ---------------------------------------------------------------------------
#define XS_STRIDE 68
#define WS_STRIDE 72
#define WS_BUF    (64 * WS_STRIDE)          // 4608 floats per buffer
#define SS_STRIDE 9
#define MAIN_SMEM_FLOATS (128 * XS_STRIDE + 2 * WS_BUF + 128 * SS_STRIDE)

__global__ __launch_bounds__(256, 2) void spectral_main_kernel(
    const float* __restrict__ x, const float* __restrict__ w,
    float* __restrict__ out)
{
    extern __shared__ float sm[];
    float* x_s  = sm;                            // 128 * 68
    float* Wraw = sm + 128 * XS_STRIDE;          // 2 * 4608
    float* S_s  = sm + 128 * XS_STRIDE + 2 * WS_BUF;

    const int tid  = threadIdx.x;
    const int h    = blockIdx.y;
    const int bt0  = blockIdx.x * 128;

    const int lane = tid & 31;
    const int wid  = tid >> 5;
    const int gid  = lane >> 2;   // 0..7
    const int tig  = lane & 3;    // 0..3
    const int wm   = wid & 3;     // m warp coord (x32)
    const int wn   = wid >> 2;    // n warp coord (x32)

    const float* Wh = w + (size_t)h * 8 * 64 * 64;   // W[h] : [512][64] row-major

    const unsigned wraw_smem =
        (unsigned)__cvta_generic_to_shared(Wraw);
    const int wr_r  = tid >> 4;       // 0..15 (row block per thread, 4 rows apart)
    const int wr_c4 = tid & 15;       // float4 column

    // ---- issue cp.async for W chunks 0 and 1 ----
#pragma unroll
    for (int c = 0; c < 2; ++c) {
        const float* src = Wh + (size_t)c * 4096;
        unsigned dbase = wraw_smem + c * (WS_BUF * 4);
#pragma unroll
        for (int j = 0; j < 4; ++j) {
            int r = wr_r + j * 16;
            cp_async16(dbase + (r * WS_STRIDE + wr_c4 * 4) * 4,
                       src + r * 64 + wr_c4 * 4);
        }
        cp_commit();
    }

    // ---- stage x tile (128 rows x 64 cols) ----
#pragma unroll
    for (int j = 0; j < 8; ++j) {
        int idx = tid + j * 256;
        int r = idx >> 4, c4 = idx & 15;
        float4 v = ((const float4*)x)[(size_t)(bt0 + r) * 256 + h * 16 + c4];
        float* d = x_s + r * XS_STRIDE + c4 * 4;
        d[0] = v.x; d[1] = v.y; d[2] = v.z; d[3] = v.w;
    }
    // ---- stage scores ----
#pragma unroll
    for (int j = 0; j < 4; ++j) {
        int idx = tid + j * 256;
        int r = idx >> 3, k = idx & 7;
        S_s[r * SS_STRIDE + k] = g_scores[(bt0 + r) * 8 + k];
    }
    __syncthreads();

    // ---- x fragments, tf32 (rna) converted ONCE ----
    unsigned xf[2][8][4];
#pragma unroll
    for (int mt = 0; mt < 2; ++mt) {
        const int t0 = wm * 32 + mt * 16 + gid;
        const int t1 = t0 + 8;
#pragma unroll
        for (int it = 0; it < 8; ++it) {
            const int i0 = it * 8 + tig;
            xf[mt][it][0] = f2tf32(x_s[t0 * XS_STRIDE + i0]);
            xf[mt][it][1] = f2tf32(x_s[t1 * XS_STRIDE + i0]);
            xf[mt][it][2] = f2tf32(x_s[t0 * XS_STRIDE + i0 + 4]);
            xf[mt][it][3] = f2tf32(x_s[t1 * XS_STRIDE + i0 + 4]);
        }
    }

    float acc[2][4][4];
#pragma unroll
    for (int mt = 0; mt < 2; ++mt)
#pragma unroll
        for (int nt = 0; nt < 4; ++nt)
#pragma unroll
            for (int r = 0; r < 4; ++r) acc[mt][nt][r] = 0.f;

#pragma unroll 1
    for (int k = 0; k < 8; ++k) {
        if (k < 7) cp_wait<1>(); else cp_wait<0>();
        __syncthreads();   // W chunk k visible to all warps

        const int tb = wm * 32 + gid;
        const float s00 = S_s[(tb)      * SS_STRIDE + k];
        const float s01 = S_s[(tb + 8)  * SS_STRIDE + k];
        const float s10 = S_s[(tb + 16) * SS_STRIDE + k];
        const float s11 = S_s[(tb + 24) * SS_STRIDE + k];

        // raw f32 bits fed to mma.tf32 (HW uses the tf32 field = RZ truncation)
        const unsigned* Wb = (const unsigned*)(Wraw + (k & 1) * WS_BUF);
        const int colbase = tig * WS_STRIDE + wn * 32 + gid;

#pragma unroll
        for (int nt = 0; nt < 4; ++nt) {
            float a0c[4], a1c[4];
#pragma unroll
            for (int it = 0; it < 8; ++it) {
                const int r0 = colbase + it * (8 * WS_STRIDE) + nt * 8;
                unsigned b0 = Wb[r0];
                unsigned b1 = Wb[r0 + 4 * WS_STRIDE];
                if (it == 0) {
                    mma_tf32_set(a0c[0], a0c[1], a0c[2], a0c[3],
                                 xf[0][it][0], xf[0][it][1], xf[0][it][2], xf[0][it][3], b0, b1);
                    mma_tf32_set(a1c[0], a1c[1], a1c[2], a1c[3],
                                 xf[1][it][0], xf[1][it][1], xf[1][it][2], xf[1][it][3], b0, b1);
                } else {
                    mma_tf32_acc(a0c[0], a0c[1], a0c[2], a0c[3],
                                 xf[0][it][0], xf[0][it][1], xf[0][it][2], xf[0][it][3], b0, b1);
                    mma_tf32_acc(a1c[0], a1c[1], a1c[2], a1c[3],
                                 xf[1][it][0], xf[1][it][1], xf[1][it][2], xf[1][it][3], b0, b1);
                }
            }
            // acc += S[t,k] * Y_k
            acc[0][nt][0] = fmaf(s00, a0c[0], acc[0][nt][0]);
            acc[0][nt][1] = fmaf(s00, a0c[1], acc[0][nt][1]);
            acc[0][nt][2] = fmaf(s01, a0c[2], acc[0][nt][2]);
            acc[0][nt][3] = fmaf(s01, a0c[3], acc[0][nt][3]);
            acc[1][nt][0] = fmaf(s10, a1c[0], acc[1][nt][0]);
            acc[1][nt][1] = fmaf(s10, a1c[1], acc[1][nt][1]);
            acc[1][nt][2] = fmaf(s11, a1c[2], acc[1][nt][2]);
            acc[1][nt][3] = fmaf(s11, a1c[3], acc[1][nt][3]);
        }

        __syncthreads();   // all warps done with buffer (k&1)
        if (k < 6) {
            const float* src = Wh + (size_t)(k + 2) * 4096;
            unsigned dbase = wraw_smem + (k & 1) * (WS_BUF * 4);
#pragma unroll
            for (int j = 0; j < 4; ++j) {
                int r = wr_r + j * 16;
                cp_async16(dbase + (r * WS_STRIDE + wr_c4 * 4) * 4,
                           src + r * 64 + wr_c4 * 4);
            }
            cp_commit();
        }
    }

    // ---- epilogue: fp32 store ----
#pragma unroll
    for (int mt = 0; mt < 2; ++mt) {
        const int t0 = bt0 + wm * 32 + mt * 16 + gid;
#pragma unroll
        for (int nt = 0; nt < 4; ++nt) {
            const int o = h * 64 + wn * 32 + nt * 8 + tig * 2;
            *(float2*)(out + (size_t)t0 * 1024 + o) =
                make_float2(acc[mt][nt][0], acc[mt][nt][1]);
            *(float2*)(out + (size_t)(t0 + 8) * 1024 + o) =
                make_float2(acc[mt][nt][2], acc[mt][nt][3]);
        }
    }
}

// ---------------------------------------------------------------------------
extern "C" void kernel_launch(void* const* d_in, const int* in_sizes, int n_in,
                              void* d_out, int out_size) {
    const float* x    = (const float*)d_in[0];   // [4,2048,1024]
    const float* wgt  = (const float*)d_in[1];   // [16,8,64,64]
    const float* diag = (const float*)d_in[2];   // [8,1024]
    const float* phi  = (const float*)d_in[3];   // [2048,8]
    float* out = (float*)d_out;                  // [4,2048,1024]

    const int main_smem = MAIN_SMEM_FLOATS * 4;
    cudaFuncSetAttribute(spectral_main_kernel,
                         cudaFuncAttributeMaxDynamicSharedMemorySize, main_smem);

    scores_kernel<<<256, 256>>>(x, diag, phi);
    spectral_main_kernel<<<dim3(64, 16), 256, main_smem>>>(x, wgt, out);
}